// round 9
// baseline (speedup 1.0000x reference)
#include <cuda_runtime.h>
#include <cuda_fp16.h>
#include <cstdint>
#include <cstddef>

#define DINL __device__ __forceinline__

static constexpr int KCHUNK   = 32;              // K elems per chunk
static constexpr int ROW_B    = 80;              // smem row stride bytes (64B data + 16 pad)
static constexpr int TILE_B   = 128 * ROW_B;     // 10240 B per fp16 tile
static constexpr int A_STAGES = 2;
static constexpr int B_STAGES = 4;
static constexpr int SMEM_BYTES = (A_STAGES + B_STAGES) * TILE_B;   // 61440 -> 2 CTAs/SM

static constexpr int M_TOTAL = 16384;
static constexpr int D_IN    = 512;
static constexpr int D_OUT   = 128;
static constexpr int NTILES  = M_TOTAL / 128;    // 128 output tiles

// Hybrid split schedule: coarse tiles at KSPLIT=8, tail tiles at KSPLIT=16.
static constexpr int COARSE_TILES = 112;
static constexpr int FINE_TILES   = NTILES - COARSE_TILES;    // 16
static constexpr int CH_COARSE    = 64;          // chunks per coarse unit (K=2048)
static constexpr int CH_FINE      = 32;          // chunks per fine unit   (K=1024)
static constexpr int COARSE_UNITS = COARSE_TILES * 8;         // 896
static constexpr int FINE_UNITS   = FINE_TILES * 16;          // 256
static constexpr int UNITS_TOTAL  = COARSE_UNITS + FINE_UNITS;// 1152
static constexpr int KSPLIT_MAX   = 16;

// Static scratch (allocation-free).
__device__ __half g_xT[(size_t)D_OUT * M_TOTAL];                 // x^T fp16 [128][16384]
__device__ __half g_WT[(size_t)D_OUT * D_IN];                    // W^T fp16 [128][512]
__device__ float  g_part[(size_t)KSPLIT_MAX * M_TOTAL * D_OUT];  // split-K partial planes
__device__ unsigned g_ticket;
__device__ unsigned g_tdone[NTILES];

// ---------------------------------------------------------------- helpers
DINL uint32_t smem_u32(const void* p) {
    uint32_t a;
    asm("{ .reg .u64 t; cvta.to.shared.u64 t, %1; cvt.u32.u64 %0, t; }"
        : "=r"(a) : "l"(p));
    return a;
}
DINL void cp16(uint32_t saddr, const void* g) {
    asm volatile("cp.async.cg.shared.global [%0], [%1], 16;"
                 :: "r"(saddr), "l"(g));
}
DINL uint32_t pack_h2(float lo, float hi) {    // low half = lo
    uint32_t r;
    asm("cvt.rn.f16x2.f32 %0, %1, %2;" : "=r"(r) : "f"(hi), "f"(lo));
    return r;
}
DINL void sts64(uint32_t a, uint32_t w0, uint32_t w1) {
    asm volatile("st.shared.v2.b32 [%0], {%1, %2};" :: "r"(a), "r"(w0), "r"(w1) : "memory");
}
DINL void ldsm4(uint32_t* r, uint32_t addr) {
    asm volatile("ldmatrix.sync.aligned.m8n8.x4.shared.b16 {%0,%1,%2,%3}, [%4];"
                 : "=r"(r[0]), "=r"(r[1]), "=r"(r[2]), "=r"(r[3]) : "r"(addr));
}
DINL void mma_f16(float* c, const uint32_t* a, const uint32_t* b) {
    asm volatile(
        "mma.sync.aligned.m16n8k16.row.col.f32.f16.f16.f32 "
        "{%0,%1,%2,%3}, {%4,%5,%6,%7}, {%8,%9}, {%0,%1,%2,%3};"
        : "+f"(c[0]), "+f"(c[1]), "+f"(c[2]), "+f"(c[3])
        : "r"(a[0]), "r"(a[1]), "r"(a[2]), "r"(a[3]), "r"(b[0]), "r"(b[1]));
}

// ---------------------------------------------------------------- kernels
// W[512][128] -> WT fp16 [128][512]; resets ticket + tile-done counters.
__global__ void transposeW_kernel(const float* __restrict__ W, __half* __restrict__ WT) {
    if (blockIdx.x == 0) {
        if (threadIdx.x == 0) g_ticket = 0u;
        if (threadIdx.x < NTILES) g_tdone[threadIdx.x] = 0u;
    }
    int t = blockIdx.x * blockDim.x + threadIdx.x;   // 65536 threads
    int k = t >> 7, n = t & 127;
    WT[(size_t)n * D_IN + k] = __float2half_rn(W[(size_t)k * D_OUT + n]);
}

// C-tile(128x128) = A[128,K](fp32) @ B[128,K](fp16)^T.  128 threads, warp grid 2x2,
// warp tile 64x64.  A: LDG->regs->fp16 STS (2-stage ring, one chunk ahead).
// B: cp.async 4-stage ring.
// QUEUE: persistent, tile-major hybrid tickets (coarse KSPLIT=8, fine KSPLIT=16);
//        the last finisher of a tile sums its partial planes in fixed order -> out.
// TRANS_EPI: write C^T as fp16 (xT for GEMM2).
template <bool TRANS_EPI, bool QUEUE>
__global__ void __launch_bounds__(128, 2)
gemm_f16(const float* __restrict__ A, const __half* __restrict__ B,
         float* __restrict__ C, float* __restrict__ out, int K, int nchunks_p)
{
    extern __shared__ __align__(16) char smem[];
    __shared__ unsigned s_unit;
    const uint32_t sA = smem_u32(smem);                  // 2 fp16 A stages
    const uint32_t sB = sA + A_STAGES * TILE_B;          // 4 fp16 B stages
    const int tid  = threadIdx.x;
    const int wid  = tid >> 5, lane = tid & 31;
    const int mw   = (wid >> 1) * 64;                    // 2 m warp-groups
    const int nw   = (wid & 1)  * 64;                    // 2 n warp-groups
    const int rg   = lane >> 2;                          // mma row group
    const int cc   = (lane & 3) * 2;                     // mma col pair base
    // ldmatrix per-lane address components
    const int a_r  = (lane & 7) + ((lane >> 3) & 1) * 8; // A: groups 1,3 -> +8 rows
    const int a_k  = (lane >> 4) * 16;                   // A: groups 2,3 -> +16B k
    const int b_r  = (lane & 7) + ((lane >> 4) & 1) * 8; // B: groups 2,3 -> +8 rows
    const int b_k  = ((lane >> 3) & 1) * 16;             // B: groups 1,3 -> +16B k
    // A LDG/STS granules: 8 x 16B fp32 -> 8 x 8B fp16 per thread
    int arow[8], acol[8];
#pragma unroll
    for (int g = 0; g < 8; ++g) { int idx = tid + 128 * g; arow[g] = idx >> 3; acol[g] = idx & 7; }
    // B cp.async granules: 4 x 16B fp16 per thread
    int brow[4], bcol[4];
#pragma unroll
    for (int g = 0; g < 4; ++g) { int idx = tid + 128 * g; brow[g] = idx >> 2; bcol[g] = idx & 3; }

    for (;;) {
        int mt, ks, nchunks, ksplit;
        if (QUEUE) {
            if (tid == 0) s_unit = atomicAdd(&g_ticket, 1u);
            __syncthreads();
            unsigned u = s_unit;
            if (u >= (unsigned)UNITS_TOTAL) return;
            if (u < (unsigned)COARSE_UNITS) {            // coarse: KSPLIT=8
                mt = (int)(u >> 3); ks = (int)(u & 7u);
                nchunks = CH_COARSE; ksplit = 8;
            } else {                                     // fine tail: KSPLIT=16
                unsigned v = u - COARSE_UNITS;
                mt = COARSE_TILES + (int)(v >> 4); ks = (int)(v & 15u);
                nchunks = CH_FINE; ksplit = 16;
            }
        } else {
            mt = blockIdx.x; ks = 0; nchunks = nchunks_p; ksplit = 1;
        }

        const float*  a0 = A + (size_t)mt * 128 * K + (size_t)ks * nchunks * KCHUNK;
        const __half* b0 = B + (size_t)ks * nchunks * KCHUNK;

        auto ldg_A = [&](int chunk, float4* st) {
            const float* ga = a0 + (size_t)chunk * KCHUNK;
#pragma unroll
            for (int g = 0; g < 8; ++g)
                st[g] = *(const float4*)(ga + (size_t)arow[g] * K + acol[g] * 4);
        };
        auto sts_A = [&](int chunk, const float4* st) {
            uint32_t abuf = sA + (chunk & 1) * TILE_B;
#pragma unroll
            for (int g = 0; g < 8; ++g) {
                uint32_t w0 = pack_h2(st[g].x, st[g].y);
                uint32_t w1 = pack_h2(st[g].z, st[g].w);
                sts64(abuf + arow[g] * ROW_B + acol[g] * 8, w0, w1);
            }
        };
        auto cp_B = [&](int chunk) {
            const __half* gb = b0 + (size_t)chunk * KCHUNK;
            uint32_t dst = sB + (chunk & (B_STAGES - 1)) * TILE_B;
#pragma unroll
            for (int g = 0; g < 4; ++g)
                cp16(dst + brow[g] * ROW_B + bcol[g] * 16,
                     gb + (size_t)brow[g] * K + bcol[g] * 8);
        };

        float acc[4][8][4];
#pragma unroll
        for (int i = 0; i < 4; ++i)
#pragma unroll
            for (int j = 0; j < 8; ++j)
#pragma unroll
                for (int f = 0; f < 4; ++f) acc[i][j][f] = 0.f;

        float4 st[8];
        ldg_A(0, st);
        sts_A(0, st);                       // stage 0; drained by first sync
        if (nchunks > 1) ldg_A(1, st);      // held in regs until iter 0
        cp_B(0); asm volatile("cp.async.commit_group;" ::: "memory");
        if (nchunks > 1) cp_B(1);
        asm volatile("cp.async.commit_group;" ::: "memory");
        if (nchunks > 2) cp_B(2);
        asm volatile("cp.async.commit_group;" ::: "memory");

        for (int kc = 0; kc < nchunks; ++kc) {
            asm volatile("cp.async.wait_group 2;" ::: "memory");   // B(kc) ready
            __syncthreads();   // readers of stage (kc+1)&1 done; A(kc)/B(kc) visible
            // A(kc+1) -> stage (kc+1)&1 (regs loaded last iteration)
            if (kc + 1 < nchunks) sts_A(kc + 1, st);
            if (kc + 2 < nchunks) ldg_A(kc + 2, st);
            if (kc + 3 < nchunks) cp_B(kc + 3);
            asm volatile("cp.async.commit_group;" ::: "memory");

            const uint32_t abuf = sA + (kc & 1) * TILE_B;
            const uint32_t bbuf = sB + (kc & (B_STAGES - 1)) * TILE_B;
#pragma unroll
            for (int kk = 0; kk < 2; ++kk) {
                uint32_t a[4][4];
#pragma unroll
                for (int i = 0; i < 4; ++i)
                    ldsm4(a[i], abuf + (mw + i * 16 + a_r) * ROW_B + a_k + kk * 32);
                uint32_t b[4][4];
#pragma unroll
                for (int jp = 0; jp < 4; ++jp)
                    ldsm4(b[jp], bbuf + (nw + jp * 16 + b_r) * ROW_B + b_k + kk * 32);
#pragma unroll
                for (int i = 0; i < 4; ++i)
#pragma unroll
                    for (int j = 0; j < 8; ++j)
                        mma_f16(acc[i][j], a[i], &b[j >> 1][(j & 1) * 2]);
            }
        }

        // Epilogue
#pragma unroll
        for (int i = 0; i < 4; ++i) {
            const int rloc = mw + i * 16 + rg;
#pragma unroll
            for (int j = 0; j < 8; ++j) {
                const int col = nw + j * 8 + cc;
                if (TRANS_EPI) {           // write x^T as fp16
                    __half* X = reinterpret_cast<__half*>(C);
                    const int grow = mt * 128 + rloc;
                    X[(size_t)col       * M_TOTAL + grow]     = __float2half_rn(acc[i][j][0]);
                    X[(size_t)(col + 1) * M_TOTAL + grow]     = __float2half_rn(acc[i][j][1]);
                    X[(size_t)col       * M_TOTAL + grow + 8] = __float2half_rn(acc[i][j][2]);
                    X[(size_t)(col + 1) * M_TOTAL + grow + 8] = __float2half_rn(acc[i][j][3]);
                } else {
                    float* cb = C + (size_t)ks * M_TOTAL * D_OUT + (size_t)mt * 128 * D_OUT;
                    *(float2*)(cb + (size_t)rloc * D_OUT + col) =
                        make_float2(acc[i][j][0], acc[i][j][1]);
                    *(float2*)(cb + (size_t)(rloc + 8) * D_OUT + col) =
                        make_float2(acc[i][j][2], acc[i][j][3]);
                }
            }
        }
        if (!QUEUE) return;

        // Tile-done accounting; last finisher reduces the tile (fixed plane order).
        __threadfence();                   // partial stores visible chip-wide
        __syncthreads();                   // all warps' stores issued before count
        if (tid == 0) s_unit = atomicAdd(&g_tdone[mt], 1u);
        __syncthreads();
        if (s_unit == (unsigned)(ksplit - 1)) {
            __threadfence();               // see all partial planes
            const size_t tbase = (size_t)mt * 128 * D_OUT / 4;
            const size_t kstr  = (size_t)M_TOTAL * D_OUT / 4;
            const float4* p = reinterpret_cast<const float4*>(g_part) + tbase;
            float4* o = reinterpret_cast<float4*>(out) + tbase;
            for (int i = tid; i < 128 * D_OUT / 4; i += 128) {
                float4 s = p[i];
                for (int k = 1; k < ksplit; ++k) {
                    float4 t = p[i + (size_t)k * kstr];
                    s.x += t.x; s.y += t.y; s.z += t.z; s.w += t.w;
                }
                o[i] = s;
            }
        }
        __syncthreads();                   // s_unit reuse guard
    }
}

// ---------------------------------------------------------------- launch
extern "C" void kernel_launch(void* const* d_in, const int* in_sizes, int n_in,
                              void* d_out, int out_size)
{
    const float* inputs = nullptr;
    const float* adj = nullptr;
    const float* weights = nullptr;
    for (int i = 0; i < n_in; ++i) {
        long sz = (long)in_sizes[i];
        if (sz == (long)M_TOTAL * D_IN)         inputs  = (const float*)d_in[i];
        else if (sz == (long)M_TOTAL * M_TOTAL) adj     = (const float*)d_in[i];
        else if (sz == (long)D_IN * D_OUT)      weights = (const float*)d_in[i];
    }

    __half *xT = nullptr, *WT = nullptr;
    float  *part = nullptr;
    cudaGetSymbolAddress((void**)&xT, g_xT);
    cudaGetSymbolAddress((void**)&WT, g_WT);
    cudaGetSymbolAddress((void**)&part, g_part);
    cudaFuncSetAttribute((const void*)gemm_f16<true,  false>,
                         cudaFuncAttributeMaxDynamicSharedMemorySize, SMEM_BYTES);
    cudaFuncSetAttribute((const void*)gemm_f16<false, true>,
                         cudaFuncAttributeMaxDynamicSharedMemorySize, SMEM_BYTES);

    // 1) WT = fp16(W^T); reset ticket + done counters
    transposeW_kernel<<<(D_IN * D_OUT) / 256, 256>>>(weights, WT);
    // 2) xT = fp16((inputs @ W)^T)
    gemm_f16<true,  false><<<M_TOTAL / 128, 128, SMEM_BYTES>>>(
        inputs, WT, (float*)xT, nullptr, D_IN, D_IN / KCHUNK);
    // 3) out = adj @ x  (persistent, hybrid split-K, fused deterministic reduction)
    gemm_f16<false, true><<<296, 128, SMEM_BYTES>>>(
        adj, xT, part, (float*)d_out, M_TOTAL, 0);
}

// round 11
// speedup vs baseline: 1.1566x; 1.1566x over previous
#include <cuda_runtime.h>
#include <cuda_fp16.h>
#include <cstdint>
#include <cstddef>

#define DINL __device__ __forceinline__

static constexpr int KCHUNK   = 32;              // K elems per chunk
static constexpr int ROW_B    = 80;              // smem row stride bytes (64B data + 16 pad)
static constexpr int TILE_B   = 128 * ROW_B;     // 10240 B per fp16 tile
static constexpr int A_STAGES = 2;
static constexpr int B_STAGES = 4;
static constexpr int SMEM_BYTES = (A_STAGES + B_STAGES) * TILE_B;   // 61440 -> 2 CTAs/SM

static constexpr int M_TOTAL = 16384;
static constexpr int D_IN    = 512;
static constexpr int D_OUT   = 128;
static constexpr int KSPLIT  = 16;
static constexpr int CH_UNIT = (M_TOTAL / KCHUNK) / KSPLIT;   // 32 chunks / unit
static constexpr int UNITS   = (M_TOTAL / 128) * KSPLIT;      // 2048 units

// Static scratch (allocation-free).
__device__ __half g_xT[(size_t)D_OUT * M_TOTAL];              // x^T fp16 [128][16384]
__device__ __half g_WT[(size_t)D_OUT * D_IN];                 // W^T fp16 [128][512]
__device__ float  g_part[(size_t)KSPLIT * M_TOTAL * D_OUT];   // split-K partials (128 MB)
__device__ unsigned g_ticket;

// ---------------------------------------------------------------- helpers
DINL uint32_t smem_u32(const void* p) {
    uint32_t a;
    asm("{ .reg .u64 t; cvta.to.shared.u64 t, %1; cvt.u32.u64 %0, t; }"
        : "=r"(a) : "l"(p));
    return a;
}
DINL void cp16(uint32_t saddr, const void* g) {
    asm volatile("cp.async.cg.shared.global [%0], [%1], 16;"
                 :: "r"(saddr), "l"(g));
}
DINL uint32_t pack_h2(float lo, float hi) {    // low half = lo
    uint32_t r;
    asm("cvt.rn.f16x2.f32 %0, %1, %2;" : "=r"(r) : "f"(hi), "f"(lo));
    return r;
}
DINL void sts64(uint32_t a, uint32_t w0, uint32_t w1) {
    asm volatile("st.shared.v2.b32 [%0], {%1, %2};" :: "r"(a), "r"(w0), "r"(w1) : "memory");
}
DINL void ldsm4(uint32_t* r, uint32_t addr) {
    asm volatile("ldmatrix.sync.aligned.m8n8.x4.shared.b16 {%0,%1,%2,%3}, [%4];"
                 : "=r"(r[0]), "=r"(r[1]), "=r"(r[2]), "=r"(r[3]) : "r"(addr));
}
DINL void mma_f16(float* c, const uint32_t* a, const uint32_t* b) {
    asm volatile(
        "mma.sync.aligned.m16n8k16.row.col.f32.f16.f16.f32 "
        "{%0,%1,%2,%3}, {%4,%5,%6,%7}, {%8,%9}, {%0,%1,%2,%3};"
        : "+f"(c[0]), "+f"(c[1]), "+f"(c[2]), "+f"(c[3])
        : "r"(a[0]), "r"(a[1]), "r"(a[2]), "r"(a[3]), "r"(b[0]), "r"(b[1]));
}

// ---------------------------------------------------------------- kernels
// W[512][128] -> WT fp16 [128][512]; resets the ticket.
__global__ void transposeW_kernel(const float* __restrict__ W, __half* __restrict__ WT) {
    if (blockIdx.x == 0 && threadIdx.x == 0) g_ticket = 0u;
    int t = blockIdx.x * blockDim.x + threadIdx.x;   // 65536 threads
    int k = t >> 7, n = t & 127;
    WT[(size_t)n * D_IN + k] = __float2half_rn(W[(size_t)k * D_OUT + n]);
}

// C-tile(128x128) = A[128,K](fp32) @ B[128,K](fp16)^T.  128 threads, warp grid 2x2,
// warp tile 64x64.  A: LDG->regs->fp16 STS (2-stage ring, stored one chunk ahead).
// B: cp.async 4-stage ring.  QUEUE: persistent ticket, ks-major (mt = u&127,
// ks = u>>7) so concurrent CTAs share the same B slice (L2 reuse) -> g_part.
// TRANS_EPI: write C^T as fp16 (xT for GEMM2).
template <bool TRANS_EPI, bool QUEUE>
__global__ void __launch_bounds__(128, 2)
gemm_f16(const float* __restrict__ A, const __half* __restrict__ B,
         float* __restrict__ C, int K, int nchunks)
{
    extern __shared__ __align__(16) char smem[];
    __shared__ unsigned s_unit;
    const uint32_t sA = smem_u32(smem);                  // 2 fp16 A stages
    const uint32_t sB = sA + A_STAGES * TILE_B;          // 4 fp16 B stages
    const int tid  = threadIdx.x;
    const int wid  = tid >> 5, lane = tid & 31;
    const int mw   = (wid >> 1) * 64;                    // 2 m warp-groups
    const int nw   = (wid & 1)  * 64;                    // 2 n warp-groups
    const int rg   = lane >> 2;                          // mma row group
    const int cc   = (lane & 3) * 2;                     // mma col pair base
    // ldmatrix per-lane address components
    const int a_r  = (lane & 7) + ((lane >> 3) & 1) * 8; // A: groups 1,3 -> +8 rows
    const int a_k  = (lane >> 4) * 16;                   // A: groups 2,3 -> +16B k
    const int b_r  = (lane & 7) + ((lane >> 4) & 1) * 8; // B: groups 2,3 -> +8 rows
    const int b_k  = ((lane >> 3) & 1) * 16;             // B: groups 1,3 -> +16B k
    // A LDG/STS granules: 8 x 16B fp32 -> 8 x 8B fp16 per thread
    int arow[8], acol[8];
#pragma unroll
    for (int g = 0; g < 8; ++g) { int idx = tid + 128 * g; arow[g] = idx >> 3; acol[g] = idx & 7; }
    // B cp.async granules: 4 x 16B fp16 per thread
    int brow[4], bcol[4];
#pragma unroll
    for (int g = 0; g < 4; ++g) { int idx = tid + 128 * g; brow[g] = idx >> 2; bcol[g] = idx & 3; }

    for (;;) {
        int mt, ks;
        if (QUEUE) {
            if (tid == 0) s_unit = atomicAdd(&g_ticket, 1u);
            __syncthreads();
            unsigned u = s_unit;
            if (u >= (unsigned)UNITS) return;
            mt = (int)(u & 127u); ks = (int)(u >> 7);    // ks-major: B-slice L2 reuse
        } else {
            mt = blockIdx.x; ks = 0;
        }

        const float*  a0 = A + (size_t)mt * 128 * K + (size_t)ks * CH_UNIT * KCHUNK;
        const __half* b0 = B + (size_t)ks * CH_UNIT * KCHUNK;

        auto ldg_A = [&](int chunk, float4* st) {
            const float* ga = a0 + (size_t)chunk * KCHUNK;
#pragma unroll
            for (int g = 0; g < 8; ++g)
                st[g] = *(const float4*)(ga + (size_t)arow[g] * K + acol[g] * 4);
        };
        auto sts_A = [&](int chunk, const float4* st) {
            uint32_t abuf = sA + (chunk & 1) * TILE_B;
#pragma unroll
            for (int g = 0; g < 8; ++g) {
                uint32_t w0 = pack_h2(st[g].x, st[g].y);
                uint32_t w1 = pack_h2(st[g].z, st[g].w);
                sts64(abuf + arow[g] * ROW_B + acol[g] * 8, w0, w1);
            }
        };
        auto cp_B = [&](int chunk) {
            const __half* gb = b0 + (size_t)chunk * KCHUNK;
            uint32_t dst = sB + (chunk & (B_STAGES - 1)) * TILE_B;
#pragma unroll
            for (int g = 0; g < 4; ++g)
                cp16(dst + brow[g] * ROW_B + bcol[g] * 16,
                     gb + (size_t)brow[g] * K + bcol[g] * 8);
        };

        float acc[4][8][4];
#pragma unroll
        for (int i = 0; i < 4; ++i)
#pragma unroll
            for (int j = 0; j < 8; ++j)
#pragma unroll
                for (int f = 0; f < 4; ++f) acc[i][j][f] = 0.f;

        float4 st[8];
        ldg_A(0, st);
        sts_A(0, st);                       // stage 0; drained by first sync
        if (nchunks > 1) ldg_A(1, st);      // held in regs until iter 0
        cp_B(0); asm volatile("cp.async.commit_group;" ::: "memory");
        if (nchunks > 1) cp_B(1);
        asm volatile("cp.async.commit_group;" ::: "memory");
        if (nchunks > 2) cp_B(2);
        asm volatile("cp.async.commit_group;" ::: "memory");

        for (int kc = 0; kc < nchunks; ++kc) {
            asm volatile("cp.async.wait_group 2;" ::: "memory");   // B(kc) ready
            __syncthreads();   // readers of stage (kc+1)&1 done; A(kc)/B(kc) visible
            // A(kc+1) -> stage (kc+1)&1 (regs loaded last iteration)
            if (kc + 1 < nchunks) sts_A(kc + 1, st);
            if (kc + 2 < nchunks) ldg_A(kc + 2, st);
            if (kc + 3 < nchunks) cp_B(kc + 3);
            asm volatile("cp.async.commit_group;" ::: "memory");

            const uint32_t abuf = sA + (kc & 1) * TILE_B;
            const uint32_t bbuf = sB + (kc & (B_STAGES - 1)) * TILE_B;
#pragma unroll
            for (int kk = 0; kk < 2; ++kk) {
                uint32_t a[4][4];
#pragma unroll
                for (int i = 0; i < 4; ++i)
                    ldsm4(a[i], abuf + (mw + i * 16 + a_r) * ROW_B + a_k + kk * 32);
                uint32_t b[4][4];
#pragma unroll
                for (int jp = 0; jp < 4; ++jp)
                    ldsm4(b[jp], bbuf + (nw + jp * 16 + b_r) * ROW_B + b_k + kk * 32);
#pragma unroll
                for (int i = 0; i < 4; ++i)
#pragma unroll
                    for (int j = 0; j < 8; ++j)
                        mma_f16(acc[i][j], a[i], &b[j >> 1][(j & 1) * 2]);
            }
        }

        // Epilogue
#pragma unroll
        for (int i = 0; i < 4; ++i) {
            const int rloc = mw + i * 16 + rg;
#pragma unroll
            for (int j = 0; j < 8; ++j) {
                const int col = nw + j * 8 + cc;
                if (TRANS_EPI) {           // write x^T as fp16
                    __half* X = reinterpret_cast<__half*>(C);
                    const int grow = mt * 128 + rloc;
                    X[(size_t)col       * M_TOTAL + grow]     = __float2half_rn(acc[i][j][0]);
                    X[(size_t)(col + 1) * M_TOTAL + grow]     = __float2half_rn(acc[i][j][1]);
                    X[(size_t)col       * M_TOTAL + grow + 8] = __float2half_rn(acc[i][j][2]);
                    X[(size_t)(col + 1) * M_TOTAL + grow + 8] = __float2half_rn(acc[i][j][3]);
                } else {
                    float* cb = C + (size_t)ks * M_TOTAL * D_OUT + (size_t)mt * 128 * D_OUT;
                    *(float2*)(cb + (size_t)rloc * D_OUT + col) =
                        make_float2(acc[i][j][0], acc[i][j][1]);
                    *(float2*)(cb + (size_t)(rloc + 8) * D_OUT + col) =
                        make_float2(acc[i][j][2], acc[i][j][3]);
                }
            }
        }
        if (!QUEUE) return;
        __syncthreads();   // all lanes done with s_unit before next ticket write
    }
}

// out = sum over KSPLIT partials (fixed order, deterministic)
__global__ void reduce_kernel(float* __restrict__ out) {
    const size_t i = (size_t)blockIdx.x * blockDim.x + threadIdx.x;  // 524288 f4
    const float4* p = reinterpret_cast<const float4*>(g_part);
    const size_t stride = (size_t)M_TOTAL * D_OUT / 4;
    float4 s = p[i];
#pragma unroll
    for (int k = 1; k < KSPLIT; ++k) {
        float4 t = p[i + (size_t)k * stride];
        s.x += t.x; s.y += t.y; s.z += t.z; s.w += t.w;
    }
    reinterpret_cast<float4*>(out)[i] = s;
}

// ---------------------------------------------------------------- launch
extern "C" void kernel_launch(void* const* d_in, const int* in_sizes, int n_in,
                              void* d_out, int out_size)
{
    const float* inputs = nullptr;
    const float* adj = nullptr;
    const float* weights = nullptr;
    for (int i = 0; i < n_in; ++i) {
        long sz = (long)in_sizes[i];
        if (sz == (long)M_TOTAL * D_IN)         inputs  = (const float*)d_in[i];
        else if (sz == (long)M_TOTAL * M_TOTAL) adj     = (const float*)d_in[i];
        else if (sz == (long)D_IN * D_OUT)      weights = (const float*)d_in[i];
    }

    __half *xT = nullptr, *WT = nullptr;
    float  *part = nullptr;
    cudaGetSymbolAddress((void**)&xT, g_xT);
    cudaGetSymbolAddress((void**)&WT, g_WT);
    cudaGetSymbolAddress((void**)&part, g_part);
    cudaFuncSetAttribute((const void*)gemm_f16<true,  false>,
                         cudaFuncAttributeMaxDynamicSharedMemorySize, SMEM_BYTES);
    cudaFuncSetAttribute((const void*)gemm_f16<false, true>,
                         cudaFuncAttributeMaxDynamicSharedMemorySize, SMEM_BYTES);

    // 1) WT = fp16(W^T); reset ticket
    transposeW_kernel<<<(D_IN * D_OUT) / 256, 256>>>(weights, WT);
    // 2) xT = fp16((inputs @ W)^T)
    gemm_f16<true,  false><<<M_TOTAL / 128, 128, SMEM_BYTES>>>(
        inputs, WT, (float*)xT, D_IN, D_IN / KCHUNK);
    // 3) partials = adj @ x  (persistent, split-K=16, ks-major tickets)
    gemm_f16<false, true><<<296, 128, SMEM_BYTES>>>(
        adj, xT, part, M_TOTAL, CH_UNIT);
    // 4) out = sum partials
    reduce_kernel<<<(M_TOTAL * D_OUT / 4) / 256, 256>>>((float*)d_out);
}

// round 12
// speedup vs baseline: 1.2417x; 1.0736x over previous
#include <cuda_runtime.h>
#include <cuda_fp16.h>
#include <cstdint>
#include <cstddef>

#define DINL __device__ __forceinline__

static constexpr int KCHUNK   = 32;              // K elems per chunk
static constexpr int ROW_B    = 80;              // smem row stride bytes (64B data + 16 pad)
static constexpr int TILE_B   = 128 * ROW_B;     // 10240 B per fp16 tile
static constexpr int A_STAGES = 2;
static constexpr int B_STAGES = 4;
static constexpr int SMEM_BYTES = (A_STAGES + B_STAGES) * TILE_B;   // 61440 -> 2 CTAs/SM

static constexpr int M_TOTAL = 16384;
static constexpr int D_IN    = 512;
static constexpr int D_OUT   = 128;
static constexpr int KSPLIT  = 16;
static constexpr int CH_UNIT = (M_TOTAL / KCHUNK) / KSPLIT;   // 32 chunks / unit
static constexpr int UNITS   = (M_TOTAL / 128) * KSPLIT;      // 2048 units

// Static scratch (allocation-free).
__device__ __half g_xT[(size_t)D_OUT * M_TOTAL];               // x^T fp16 [128][16384]
__device__ __half g_WT[(size_t)D_OUT * D_IN];                  // W^T fp16 [128][512]
__device__ __half g_parth[(size_t)KSPLIT * M_TOTAL * D_OUT];   // fp16 partials (64 MB)
__device__ unsigned g_ticket;

// ---------------------------------------------------------------- helpers
DINL uint32_t smem_u32(const void* p) {
    uint32_t a;
    asm("{ .reg .u64 t; cvta.to.shared.u64 t, %1; cvt.u32.u64 %0, t; }"
        : "=r"(a) : "l"(p));
    return a;
}
DINL void cp16(uint32_t saddr, const void* g) {
    asm volatile("cp.async.cg.shared.global [%0], [%1], 16;"
                 :: "r"(saddr), "l"(g));
}
DINL uint32_t pack_h2(float lo, float hi) {    // low half = lo
    uint32_t r;
    asm("cvt.rn.f16x2.f32 %0, %1, %2;" : "=r"(r) : "f"(hi), "f"(lo));
    return r;
}
DINL void sts64(uint32_t a, uint32_t w0, uint32_t w1) {
    asm volatile("st.shared.v2.b32 [%0], {%1, %2};" :: "r"(a), "r"(w0), "r"(w1) : "memory");
}
DINL void ldsm4(uint32_t* r, uint32_t addr) {
    asm volatile("ldmatrix.sync.aligned.m8n8.x4.shared.b16 {%0,%1,%2,%3}, [%4];"
                 : "=r"(r[0]), "=r"(r[1]), "=r"(r[2]), "=r"(r[3]) : "r"(addr));
}
DINL void mma_f16(float* c, const uint32_t* a, const uint32_t* b) {
    asm volatile(
        "mma.sync.aligned.m16n8k16.row.col.f32.f16.f16.f32 "
        "{%0,%1,%2,%3}, {%4,%5,%6,%7}, {%8,%9}, {%0,%1,%2,%3};"
        : "+f"(c[0]), "+f"(c[1]), "+f"(c[2]), "+f"(c[3])
        : "r"(a[0]), "r"(a[1]), "r"(a[2]), "r"(a[3]), "r"(b[0]), "r"(b[1]));
}

// ---------------------------------------------------------------- kernels
// W[512][128] -> WT fp16 [128][512]; resets the ticket.
__global__ void transposeW_kernel(const float* __restrict__ W, __half* __restrict__ WT) {
    if (blockIdx.x == 0 && threadIdx.x == 0) g_ticket = 0u;
    int t = blockIdx.x * blockDim.x + threadIdx.x;   // 65536 threads
    int k = t >> 7, n = t & 127;
    WT[(size_t)n * D_IN + k] = __float2half_rn(W[(size_t)k * D_OUT + n]);
}

// C-tile(128x128) = A[128,K](fp32) @ B[128,K](fp16)^T.  128 threads, warp grid 2x2,
// warp tile 64x64.  A: LDG->regs->fp16 STS (2-stage ring, one chunk ahead).
// B: cp.async 4-stage ring.
// QUEUE: persistent, ks-major tickets, CONTINUOUS cross-unit pipeline (ticket for
//        unit n+1 prefetched at kc=27; last 3 iterations roll loads into the next
//        unit's chunks 0-2, same ring stages, unbroken commit-group numbering).
//        Partials written as fp16 -> g_parth.
// TRANS_EPI (QUEUE=false): write C^T as fp16 (xT for GEMM2).
template <bool TRANS_EPI, bool QUEUE>
__global__ void __launch_bounds__(128, 2)
gemm_f16(const float* __restrict__ A, const __half* __restrict__ B,
         __half* __restrict__ C, int K, int nchunks)
{
    extern __shared__ __align__(16) char smem[];
    __shared__ unsigned s_next;
    const uint32_t sA = smem_u32(smem);                  // 2 fp16 A stages
    const uint32_t sB = sA + A_STAGES * TILE_B;          // 4 fp16 B stages
    const int tid  = threadIdx.x;
    const int wid  = tid >> 5, lane = tid & 31;
    const int mw   = (wid >> 1) * 64;                    // 2 m warp-groups
    const int nw   = (wid & 1)  * 64;                    // 2 n warp-groups
    const int rg   = lane >> 2;                          // mma row group
    const int cc   = (lane & 3) * 2;                     // mma col pair base
    // ldmatrix per-lane address components
    const int a_r  = (lane & 7) + ((lane >> 3) & 1) * 8; // A: groups 1,3 -> +8 rows
    const int a_k  = (lane >> 4) * 16;                   // A: groups 2,3 -> +16B k
    const int b_r  = (lane & 7) + ((lane >> 4) & 1) * 8; // B: groups 2,3 -> +8 rows
    const int b_k  = ((lane >> 3) & 1) * 16;             // B: groups 1,3 -> +16B k
    // A LDG/STS granules: 8 x 16B fp32 -> 8 x 8B fp16 per thread
    int arow[8], acol[8];
#pragma unroll
    for (int g = 0; g < 8; ++g) { int idx = tid + 128 * g; arow[g] = idx >> 3; acol[g] = idx & 7; }
    // B cp.async granules: 4 x 16B fp16 per thread
    int brow[4], bcol[4];
#pragma unroll
    for (int g = 0; g < 4; ++g) { int idx = tid + 128 * g; brow[g] = idx >> 2; bcol[g] = idx & 3; }

    auto ldg_A = [&](const float* a0, int chunk, float4* st) {
        const float* ga = a0 + (size_t)chunk * KCHUNK;
#pragma unroll
        for (int g = 0; g < 8; ++g)
            st[g] = *(const float4*)(ga + (size_t)arow[g] * K + acol[g] * 4);
    };
    auto sts_A = [&](int chunk, const float4* st) {
        uint32_t abuf = sA + (chunk & 1) * TILE_B;
#pragma unroll
        for (int g = 0; g < 8; ++g) {
            uint32_t w0 = pack_h2(st[g].x, st[g].y);
            uint32_t w1 = pack_h2(st[g].z, st[g].w);
            sts64(abuf + arow[g] * ROW_B + acol[g] * 8, w0, w1);
        }
    };
    auto cp_B = [&](const __half* b0, int chunk) {
        const __half* gb = b0 + (size_t)chunk * KCHUNK;
        uint32_t dst = sB + (chunk & (B_STAGES - 1)) * TILE_B;
#pragma unroll
        for (int g = 0; g < 4; ++g)
            cp16(dst + brow[g] * ROW_B + bcol[g] * 16,
                 gb + (size_t)brow[g] * K + bcol[g] * 8);
    };

    float acc[4][8][4];
#pragma unroll
    for (int i = 0; i < 4; ++i)
#pragma unroll
        for (int j = 0; j < 8; ++j)
#pragma unroll
            for (int f = 0; f < 4; ++f) acc[i][j][f] = 0.f;

    // MMA step over current stages (identical instruction stream to R7)
    auto mma_step = [&](int kc) {
        const uint32_t abuf = sA + (kc & 1) * TILE_B;
        const uint32_t bbuf = sB + (kc & (B_STAGES - 1)) * TILE_B;
#pragma unroll
        for (int kk = 0; kk < 2; ++kk) {
            uint32_t a[4][4];
#pragma unroll
            for (int i = 0; i < 4; ++i)
                ldsm4(a[i], abuf + (mw + i * 16 + a_r) * ROW_B + a_k + kk * 32);
            uint32_t b[4][4];
#pragma unroll
            for (int jp = 0; jp < 4; ++jp)
                ldsm4(b[jp], bbuf + (nw + jp * 16 + b_r) * ROW_B + b_k + kk * 32);
#pragma unroll
            for (int i = 0; i < 4; ++i)
#pragma unroll
                for (int j = 0; j < 8; ++j)
                    mma_f16(acc[i][j], a[i], &b[j >> 1][(j & 1) * 2]);
        }
    };

    if constexpr (!QUEUE) {
        // ---------------- GEMM1: one tile per CTA ----------------
        const int mt = blockIdx.x;
        const float*  a0 = A + (size_t)mt * 128 * K;
        const __half* b0 = B;

        float4 st[8];
        ldg_A(a0, 0, st);
        sts_A(0, st);
        if (nchunks > 1) ldg_A(a0, 1, st);
        cp_B(b0, 0); asm volatile("cp.async.commit_group;" ::: "memory");
        if (nchunks > 1) cp_B(b0, 1);
        asm volatile("cp.async.commit_group;" ::: "memory");
        if (nchunks > 2) cp_B(b0, 2);
        asm volatile("cp.async.commit_group;" ::: "memory");

        for (int kc = 0; kc < nchunks; ++kc) {
            asm volatile("cp.async.wait_group 2;" ::: "memory");
            __syncthreads();
            if (kc + 1 < nchunks) sts_A(kc + 1, st);
            if (kc + 2 < nchunks) ldg_A(a0, kc + 2, st);
            if (kc + 3 < nchunks) cp_B(b0, kc + 3);
            asm volatile("cp.async.commit_group;" ::: "memory");
            mma_step(kc);
        }

        // write x^T as fp16
#pragma unroll
        for (int i = 0; i < 4; ++i) {
            const int rloc = mw + i * 16 + rg;
            const int grow = mt * 128 + rloc;
#pragma unroll
            for (int j = 0; j < 8; ++j) {
                const int col = nw + j * 8 + cc;
                C[(size_t)col       * M_TOTAL + grow]     = __float2half_rn(acc[i][j][0]);
                C[(size_t)(col + 1) * M_TOTAL + grow]     = __float2half_rn(acc[i][j][1]);
                C[(size_t)col       * M_TOTAL + grow + 8] = __float2half_rn(acc[i][j][2]);
                C[(size_t)(col + 1) * M_TOTAL + grow + 8] = __float2half_rn(acc[i][j][3]);
            }
        }
        return;
    } else {
        // ---------------- GEMM2: persistent, continuous pipeline ----------------
        if (tid == 0) s_next = atomicAdd(&g_ticket, 1u);
        __syncthreads();
        unsigned u = s_next;
        if (u >= (unsigned)UNITS) return;
        int mt = (int)(u & 127u), ks = (int)(u >> 7);    // ks-major: B-slice L2 reuse
        const float*  a0 = A + (size_t)mt * 128 * K + (size_t)ks * CH_UNIT * KCHUNK;
        const __half* b0 = B + (size_t)ks * CH_UNIT * KCHUNK;

        float4 st[8];
        ldg_A(a0, 0, st);
        sts_A(0, st);
        ldg_A(a0, 1, st);
        cp_B(b0, 0); asm volatile("cp.async.commit_group;" ::: "memory");
        cp_B(b0, 1); asm volatile("cp.async.commit_group;" ::: "memory");
        cp_B(b0, 2); asm volatile("cp.async.commit_group;" ::: "memory");

        bool nvalid = false;
        int mtn = 0, ksn = 0;
        const float*  a0n = A;
        const __half* b0n = B;

        for (;;) {
            for (int kc = 0; kc < CH_UNIT; ++kc) {
                asm volatile("cp.async.wait_group 2;" ::: "memory");   // B(kc) ready
                __syncthreads();   // readers of A stage (kc+1)&1 and B stage (kc+3)&3 done

                if (kc + 1 < CH_UNIT)      sts_A(kc + 1, st);
                else if (nvalid)           sts_A(0, st);                 // next.0 (same stage)
                if (kc + 2 < CH_UNIT)      ldg_A(a0, kc + 2, st);
                else if (nvalid)           ldg_A(a0n, kc + 2 - CH_UNIT, st);
                if (kc + 3 < CH_UNIT)      cp_B(b0, kc + 3);
                else if (nvalid)           cp_B(b0n, kc + 3 - CH_UNIT);
                asm volatile("cp.async.commit_group;" ::: "memory");     // unconditional

                if (kc == CH_UNIT - 5 && tid == 0)
                    s_next = atomicAdd(&g_ticket, 1u);                   // visible after next sync
                if (kc == CH_UNIT - 4) {
                    unsigned un = s_next;
                    nvalid = un < (unsigned)UNITS;
                    mtn = (int)(un & 127u); ksn = (int)(un >> 7);
                    a0n = A + (size_t)mtn * 128 * K + (size_t)ksn * CH_UNIT * KCHUNK;
                    b0n = B + (size_t)ksn * CH_UNIT * KCHUNK;
                }

                mma_step(kc);
            }

            // Epilogue: fp16 partial plane (overlaps with in-flight next-unit loads)
            {
                __half* cb = C + ((size_t)ks * M_TOTAL + (size_t)mt * 128) * D_OUT;
#pragma unroll
                for (int i = 0; i < 4; ++i) {
                    const int rloc = mw + i * 16 + rg;
#pragma unroll
                    for (int j = 0; j < 8; ++j) {
                        const int col = nw + j * 8 + cc;
                        *(__half2*)(cb + (size_t)rloc * D_OUT + col) =
                            __floats2half2_rn(acc[i][j][0], acc[i][j][1]);
                        *(__half2*)(cb + (size_t)(rloc + 8) * D_OUT + col) =
                            __floats2half2_rn(acc[i][j][2], acc[i][j][3]);
                    }
                }
            }
            if (!nvalid) return;
            mt = mtn; ks = ksn; a0 = a0n; b0 = b0n;
#pragma unroll
            for (int i = 0; i < 4; ++i)
#pragma unroll
                for (int j = 0; j < 8; ++j)
#pragma unroll
                    for (int f = 0; f < 4; ++f) acc[i][j][f] = 0.f;
        }
    }
}

// out = sum over KSPLIT fp16 partial planes (fixed order, fp32, deterministic)
__global__ void reduce_kernel(float* __restrict__ out) {
    const size_t i = (size_t)blockIdx.x * blockDim.x + threadIdx.x;  // 524288
    const uint2* p = reinterpret_cast<const uint2*>(g_parth);
    const size_t stride = (size_t)M_TOTAL * D_OUT / 4;   // plane size in uint2 units
    float4 s = make_float4(0.f, 0.f, 0.f, 0.f);
#pragma unroll
    for (int k = 0; k < KSPLIT; ++k) {
        uint2 v = p[i + (size_t)k * stride];
        float2 f0 = __half22float2(*reinterpret_cast<__half2*>(&v.x));
        float2 f1 = __half22float2(*reinterpret_cast<__half2*>(&v.y));
        s.x += f0.x; s.y += f0.y; s.z += f1.x; s.w += f1.y;
    }
    reinterpret_cast<float4*>(out)[i] = s;
}

// ---------------------------------------------------------------- launch
extern "C" void kernel_launch(void* const* d_in, const int* in_sizes, int n_in,
                              void* d_out, int out_size)
{
    const float* inputs = nullptr;
    const float* adj = nullptr;
    const float* weights = nullptr;
    for (int i = 0; i < n_in; ++i) {
        long sz = (long)in_sizes[i];
        if (sz == (long)M_TOTAL * D_IN)         inputs  = (const float*)d_in[i];
        else if (sz == (long)M_TOTAL * M_TOTAL) adj     = (const float*)d_in[i];
        else if (sz == (long)D_IN * D_OUT)      weights = (const float*)d_in[i];
    }

    __half *xT = nullptr, *WT = nullptr, *parth = nullptr;
    cudaGetSymbolAddress((void**)&xT, g_xT);
    cudaGetSymbolAddress((void**)&WT, g_WT);
    cudaGetSymbolAddress((void**)&parth, g_parth);
    cudaFuncSetAttribute((const void*)gemm_f16<true,  false>,
                         cudaFuncAttributeMaxDynamicSharedMemorySize, SMEM_BYTES);
    cudaFuncSetAttribute((const void*)gemm_f16<false, true>,
                         cudaFuncAttributeMaxDynamicSharedMemorySize, SMEM_BYTES);

    // 1) WT = fp16(W^T); reset ticket
    transposeW_kernel<<<(D_IN * D_OUT) / 256, 256>>>(weights, WT);
    // 2) xT = fp16((inputs @ W)^T)
    gemm_f16<true,  false><<<M_TOTAL / 128, 128, SMEM_BYTES>>>(
        inputs, WT, xT, D_IN, D_IN / KCHUNK);
    // 3) fp16 partials = adj @ x  (persistent, split-K=16, continuous pipeline)
    gemm_f16<false, true><<<296, 128, SMEM_BYTES>>>(
        adj, xT, parth, M_TOTAL, CH_UNIT);
    // 4) out = sum partials
    reduce_kernel<<<(M_TOTAL * D_OUT / 4) / 256, 256>>>((float*)d_out);
}